// round 11
// baseline (speedup 1.0000x reference)
#include <cuda_runtime.h>
#include <cuda_fp16.h>
#include <cstdint>

#define NPTS   262144
#define NGRIDS 64
#define GS     64
#define CELLS  (GS*GS*GS)     // 262144
#define GPC    16             // grids per epoch (slab = 16 * 2.1MB, L2-resident)
#define NCHUNK (NGRIDS/GPC)   // 4
#define PBLK   (NPTS/256)     // 1024
#define NBINS  32768          // 32^3 spatial bins (2x2x2 cells each)
#define FSCALE 16384.0f
#define FINV   (1.0f/16384.0f)

// 8-byte chunk per (g,z,y,x): slot0 = half2(f0[x],f1[x])*FSCALE,
// slot1 = half2(f0[x+1],f1[x+1])*FSCALE (0 past the 63-edge).
__device__ uint2  g_pk[(size_t)NGRIDS * CELLS];   // 134 MB scratch
__device__ int    g_hist[NBINS];                  // zero at load; scan3 re-zeroes
__device__ int    g_binStart[NBINS];
__device__ int    g_bsum[128];
__device__ float4 g_pxs[NPTS];   // sorted points: (x, y, z, bitcast(orig idx))

__device__ __forceinline__ void st64cs(void* p, uint2 v) {
    asm volatile("st.global.cs.v2.b32 [%0], {%1,%2};"
        :: "l"(p), "r"(v.x), "r"(v.y) : "memory");
}
__device__ __forceinline__ uint2 ld64nc(const void* p) {
    uint2 v;
    asm("ld.global.nc.v2.b32 {%0,%1}, [%2];" : "=r"(v.x), "=r"(v.y) : "l"(p));
    return v;
}
__device__ __forceinline__ void st256cs_f(void* p, const float* f) {
    asm volatile("st.global.cs.v8.f32 [%0], {%1,%2,%3,%4,%5,%6,%7,%8};"
        :: "l"(p), "f"(f[0]), "f"(f[1]), "f"(f[2]), "f"(f[3]),
           "f"(f[4]), "f"(f[5]), "f"(f[6]), "f"(f[7]) : "memory");
}

__device__ __forceinline__ int point_key(float tx, float ty, float tz) {
    int qx = min(max((int)((tx + 1.0f) * 16.0f), 0), 31);
    int qy = min(max((int)((ty + 1.0f) * 16.0f), 0), 31);
    int qz = min(max((int)((tz + 1.0f) * 16.0f), 0), 31);
    return (qz * 32 + qy) * 32 + qx;   // x fastest (matches chunk layout)
}

// ---------------- sort pipeline ----------------
__global__ __launch_bounds__(256) void hist_kernel(const float* __restrict__ xs) {
    int n = blockIdx.x * 256 + threadIdx.x;
    atomicAdd(&g_hist[point_key(xs[n*3], xs[n*3+1], xs[n*3+2])], 1);
}
__global__ __launch_bounds__(256) void scan1_kernel() {
    __shared__ int s[256];
    int t = threadIdx.x;
    s[t] = g_hist[blockIdx.x * 256 + t];
    __syncthreads();
    for (int o = 128; o > 0; o >>= 1) {
        if (t < o) s[t] += s[t + o];
        __syncthreads();
    }
    if (t == 0) g_bsum[blockIdx.x] = s[0];
}
// exclusive scan of 128 totals (4 warps)
__global__ __launch_bounds__(128) void scan2_kernel() {
    __shared__ int ws[4];
    int t = threadIdx.x;
    int lane = t & 31, w = t >> 5;
    int v = g_bsum[t];
    int s = v;
    #pragma unroll
    for (int o = 1; o < 32; o <<= 1) {
        int x = __shfl_up_sync(0xffffffffu, s, o);
        if (lane >= o) s += x;
    }
    if (lane == 31) ws[w] = s;
    __syncthreads();
    if (w == 0 && lane < 4) {
        int y = ws[lane];
        #pragma unroll
        for (int o = 1; o < 4; o <<= 1) {
            int x = __shfl_up_sync(0xfu, y, o);
            if (lane >= o) y += x;
        }
        ws[lane] = y;
    }
    __syncthreads();
    int off = (w > 0) ? ws[w - 1] : 0;
    g_bsum[t] = off + s - v;   // exclusive
}
// shfl-based block scan (2 barriers)
__global__ __launch_bounds__(256) void scan3_kernel() {
    __shared__ int ws[8];
    int t = threadIdx.x;
    int lane = t & 31, w = t >> 5;
    int i = blockIdx.x * 256 + t;
    int v = g_hist[i];
    g_hist[i] = 0;             // re-zero for next replay (last reader)
    int s = v;
    #pragma unroll
    for (int o = 1; o < 32; o <<= 1) {
        int x = __shfl_up_sync(0xffffffffu, s, o);
        if (lane >= o) s += x;
    }
    if (lane == 31) ws[w] = s;
    __syncthreads();
    if (w == 0 && lane < 8) {
        int y = ws[lane];
        #pragma unroll
        for (int o = 1; o < 8; o <<= 1) {
            int x = __shfl_up_sync(0xffu, y, o);
            if (lane >= o) y += x;
        }
        ws[lane] = y;
    }
    __syncthreads();
    int off = (w > 0) ? ws[w - 1] : 0;
    g_binStart[i] = off + s - v + g_bsum[blockIdx.x];
}
__global__ __launch_bounds__(256) void scatter_kernel(const float* __restrict__ xs) {
    int n = blockIdx.x * 256 + threadIdx.x;
    float tx = xs[n*3], ty = xs[n*3+1], tz = xs[n*3+2];
    int pos = atomicAdd(&g_binStart[point_key(tx, ty, tz)], 1);
    g_pxs[pos] = make_float4(tx, ty, tz, __int_as_float(n));
}

// ---------------- repack (fp16 x-pair chunks, 8B) ----------------
__global__ __launch_bounds__(256) void repack_kernel(const float* __restrict__ fg)
{
    int idx = blockIdx.x * 256 + threadIdx.x;          // over NGRIDS*CELLS
    int g = idx >> 18;
    int c = idx & (CELLS - 1);
    int x = c & (GS - 1);
    const float* base = fg + (size_t)g * 2 * CELLS;    // [F=2, D, H, W]

    float a0 = base[c];
    float a1 = base[CELLS + c];
    float b0 = 0.0f, b1 = 0.0f;
    if (x < GS - 1) {
        b0 = base[c + 1];
        b1 = base[CELLS + c + 1];
    }
    __half2 h0 = __floats2half2_rn(a0 * FSCALE, a1 * FSCALE);
    __half2 h1 = __floats2half2_rn(b0 * FSCALE, b1 * FSCALE);
    uint2 v;
    v.x = *reinterpret_cast<unsigned*>(&h0);
    v.y = *reinterpret_cast<unsigned*>(&h1);
    st64cs(&g_pk[idx], v);
}

// ---------------- sample ----------------
__global__ __launch_bounds__(256) void sample_kernel(
    const float* __restrict__ M,      // [64, 4, 4]
    float* __restrict__ out)          // [NPTS, 128]
{
    __shared__ float sM[NGRIDS * 16];
    int tid = threadIdx.x;
    for (int i = tid; i < NGRIDS * 16; i += 256) {
        float v = M[i];
        sM[i] = ((i & 3) == 3) ? 31.5f * (v + 1.0f) : 31.5f * v;
    }
    __syncthreads();

    int chunk = blockIdx.x >> 10;              // grid epoch (L2-resident slab)
    int t     = (blockIdx.x & (PBLK - 1)) * 256 + tid;

    float4 p = g_pxs[t];                       // sorted -> warp-coherent gathers
    float tx = p.x, ty = p.y, tz = p.z;
    int n = __float_as_int(p.w);

    float res[2 * GPC];

    #pragma unroll
    for (int j = 0; j < GPC; ++j) {
        int g = chunk * GPC + j;
        const float* m = sM + g * 16;
        float px = fmaf(m[0], tx, fmaf(m[1], ty, fmaf(m[2],  tz, m[3])));
        float py = fmaf(m[4], tx, fmaf(m[5], ty, fmaf(m[6],  tz, m[7])));
        float pz = fmaf(m[8], tx, fmaf(m[9], ty, fmaf(m[10], tz, m[11])));

        float wx0, wx1, w00, w01, w10, w11;
        int r00, r01, r10, r11;

        // Sorted points -> warp-uniform branch nearly everywhere.
        bool interior = (px >= 0.0f) & (px < 63.0f) &
                        (py >= 0.0f) & (py < 63.0f) &
                        (pz >= 0.0f) & (pz < 63.0f);
        if (interior) {
            int ix = (int)px, iy = (int)py, iz = (int)pz;
            float fx = px - (float)ix;
            float fy = py - (float)iy;
            float fz = pz - (float)iz;
            wx0 = 1.0f - fx; wx1 = fx;
            float wz0 = (1.0f - fz) * FINV;
            float wz1 = fz * FINV;
            w00 = wz0 * (1.0f - fy); w01 = wz0 * fy;
            w10 = wz1 * (1.0f - fy); w11 = wz1 * fy;
            int b = (iz * GS + iy) * GS + ix;
            r00 = b;            r01 = b + GS;
            r10 = b + GS * GS;  r11 = b + GS * GS + GS;
        } else {
            float fx0 = floorf(px), fy0 = floorf(py), fz0 = floorf(pz);
            float fx = px - fx0, fy = py - fy0, fz = pz - fz0;
            int ix = (int)fx0, iy = (int)fy0, iz = (int)fz0;

            bool inx = ((unsigned)ix < 64u);
            wx0 = inx ? (1.0f - fx) : ((ix == -1) ? fx : 0.0f);
            wx1 = inx ? fx : 0.0f;
            int xc = min(max(ix, 0), 63);

            float wy0 = ((unsigned)iy       < 64u) ? (1.0f - fy) : 0.0f;
            float wy1 = ((unsigned)(iy + 1) < 64u) ? fy          : 0.0f;
            int iy0c = min(max(iy,     0), 63);
            int iy1c = min(max(iy + 1, 0), 63);

            float wz0 = ((unsigned)iz       < 64u) ? (1.0f - fz) * FINV : 0.0f;
            float wz1 = ((unsigned)(iz + 1) < 64u) ? fz          * FINV : 0.0f;
            int iz0c = min(max(iz,     0), 63);
            int iz1c = min(max(iz + 1, 0), 63);

            w00 = wz0 * wy0; w01 = wz0 * wy1;
            w10 = wz1 * wy0; w11 = wz1 * wy1;
            r00 = (iz0c * GS + iy0c) * GS + xc;
            r01 = (iz0c * GS + iy1c) * GS + xc;
            r10 = (iz1c * GS + iy0c) * GS + xc;
            r11 = (iz1c * GS + iy1c) * GS + xc;
        }

        const uint2* gp = g_pk + (size_t)g * CELLS;
        uint2 c00 = ld64nc(gp + r00);
        uint2 c01 = ld64nc(gp + r01);
        uint2 c10 = ld64nc(gp + r10);
        uint2 c11 = ld64nc(gp + r11);

        // x-interp in half2 (pair = features), y/z reduction in fp32.
        __half2 hx0 = __float2half2_rn(wx0);
        __half2 hx1 = __float2half2_rn(wx1);
        __half2 m00 = __hfma2(*reinterpret_cast<__half2*>(&c00.y), hx1,
                      __hmul2(*reinterpret_cast<__half2*>(&c00.x), hx0));
        __half2 m01 = __hfma2(*reinterpret_cast<__half2*>(&c01.y), hx1,
                      __hmul2(*reinterpret_cast<__half2*>(&c01.x), hx0));
        __half2 m10 = __hfma2(*reinterpret_cast<__half2*>(&c10.y), hx1,
                      __hmul2(*reinterpret_cast<__half2*>(&c10.x), hx0));
        __half2 m11 = __hfma2(*reinterpret_cast<__half2*>(&c11.y), hx1,
                      __hmul2(*reinterpret_cast<__half2*>(&c11.x), hx0));

        float2 f00 = __half22float2(m00);
        float2 f01 = __half22float2(m01);
        float2 f10 = __half22float2(m10);
        float2 f11 = __half22float2(m11);

        float a0 = f00.x * w00;
        a0 = fmaf(f01.x, w01, a0);
        a0 = fmaf(f10.x, w10, a0);
        a0 = fmaf(f11.x, w11, a0);
        float a1 = f00.y * w00;
        a1 = fmaf(f01.y, w01, a1);
        a1 = fmaf(f10.y, w10, a1);
        a1 = fmaf(f11.y, w11, a1);

        res[2 * j]     = a0;
        res[2 * j + 1] = a1;
    }

    float* op = out + (size_t)n * (NGRIDS * 2) + chunk * (GPC * 2);
    #pragma unroll
    for (int q = 0; q < GPC / 4; ++q)
        st256cs_f(op + 8 * q, res + 8 * q);
}

extern "C" void kernel_launch(void* const* d_in, const int* in_sizes, int n_in,
                              void* d_out, int out_size)
{
    const float* xs = (const float*)d_in[0];   // [262144, 3]
    const float* M  = (const float*)d_in[1];   // [64, 4, 4]
    const float* fg = (const float*)d_in[2];   // [64, 2, 64, 64, 64]
    float* out = (float*)d_out;                // [262144, 128]

    hist_kernel   <<<NPTS / 256, 256>>>(xs);
    scan1_kernel  <<<NBINS / 256, 256>>>();
    scan2_kernel  <<<1, 128>>>();
    scan3_kernel  <<<NBINS / 256, 256>>>();
    scatter_kernel<<<NPTS / 256, 256>>>(xs);
    repack_kernel <<<(NGRIDS * CELLS) / 256, 256>>>(fg);
    sample_kernel <<<NCHUNK * PBLK, 256>>>(M, out);
}

// round 12
// speedup vs baseline: 1.1070x; 1.1070x over previous
#include <cuda_runtime.h>
#include <cuda_fp16.h>
#include <cstdint>

#define NPTS   262144
#define NGRIDS 64
#define GS     64
#define CELLS  (GS*GS*GS)     // 262144
#define GPC    8              // grids per epoch (slab = 8 * 2.1MB, L2-resident)
#define NCHUNK (NGRIDS/GPC)   // 8
#define PBLK   (NPTS/256)     // 1024
#define NBINS  262144         // 64^3 spatial bins == grid cells
#define FSCALE 16384.0f
#define FINV   (1.0f/16384.0f)

// 8-byte chunk per (g,z,y,x): slot0 = half2(f0[x],f1[x])*FSCALE,
// slot1 = half2(f0[x+1],f1[x+1])*FSCALE (0 past the 63-edge).
__device__ uint2  g_pk[(size_t)NGRIDS * CELLS];   // 134 MB scratch
__device__ int    g_hist[NBINS];                  // zero at load; scan3 re-zeroes
__device__ int    g_binStart[NBINS];
__device__ int    g_bsum[256];
__device__ float4 g_pxs[NPTS];   // sorted points: (x, y, z, bitcast(orig idx))

__device__ __forceinline__ void st64cs(void* p, uint2 v) {
    asm volatile("st.global.cs.v2.b32 [%0], {%1,%2};"
        :: "l"(p), "r"(v.x), "r"(v.y) : "memory");
}
__device__ __forceinline__ uint2 ld64nc(const void* p) {
    uint2 v;
    asm("ld.global.nc.v2.b32 {%0,%1}, [%2];" : "=r"(v.x), "=r"(v.y) : "l"(p));
    return v;
}
__device__ __forceinline__ void st256cs_f(void* p, const float* f) {
    asm volatile("st.global.cs.v8.f32 [%0], {%1,%2,%3,%4,%5,%6,%7,%8};"
        :: "l"(p), "f"(f[0]), "f"(f[1]), "f"(f[2]), "f"(f[3]),
           "f"(f[4]), "f"(f[5]), "f"(f[6]), "f"(f[7]) : "memory");
}

__device__ __forceinline__ int point_key(float tx, float ty, float tz) {
    int qx = min(max((int)((tx + 1.0f) * 32.0f), 0), 63);
    int qy = min(max((int)((ty + 1.0f) * 32.0f), 0), 63);
    int qz = min(max((int)((tz + 1.0f) * 32.0f), 0), 63);
    return (qz * GS + qy) * GS + qx;   // x fastest (matches chunk layout)
}

// ---------------- sort pipeline ----------------
__global__ __launch_bounds__(256) void hist_kernel(const float* __restrict__ xs) {
    int n = blockIdx.x * 256 + threadIdx.x;
    atomicAdd(&g_hist[point_key(xs[n*3], xs[n*3+1], xs[n*3+2])], 1);
}

// 4 bins/thread: 256 blocks x 256 threads x 4 = 262144
__global__ __launch_bounds__(256) void scan1_kernel() {
    __shared__ int s[256];
    int t = threadIdx.x;
    int4 v = *reinterpret_cast<const int4*>(&g_hist[(blockIdx.x * 256 + t) * 4]);
    s[t] = v.x + v.y + v.z + v.w;
    __syncthreads();
    for (int o = 128; o > 0; o >>= 1) {
        if (t < o) s[t] += s[t + o];
        __syncthreads();
    }
    if (t == 0) g_bsum[blockIdx.x] = s[0];
}

// exclusive scan of 256 totals
__global__ __launch_bounds__(256) void scan2_kernel() {
    __shared__ int ws[8];
    int t = threadIdx.x;
    int lane = t & 31, w = t >> 5;
    int v = g_bsum[t];
    int s = v;
    #pragma unroll
    for (int o = 1; o < 32; o <<= 1) {
        int x = __shfl_up_sync(0xffffffffu, s, o);
        if (lane >= o) s += x;
    }
    if (lane == 31) ws[w] = s;
    __syncthreads();
    if (w == 0 && lane < 8) {
        int y = ws[lane];
        #pragma unroll
        for (int o = 1; o < 8; o <<= 1) {
            int x = __shfl_up_sync(0xffu, y, o);
            if (lane >= o) y += x;
        }
        ws[lane] = y;
    }
    __syncthreads();
    int off = (w > 0) ? ws[w - 1] : 0;
    g_bsum[t] = off + s - v;   // exclusive
}

// 4 bins/thread, shfl block scan, vectorized re-zero + binStart store
__global__ __launch_bounds__(256) void scan3_kernel() {
    __shared__ int ws[8];
    int t = threadIdx.x;
    int lane = t & 31, w = t >> 5;
    int i4 = (blockIdx.x * 256 + t) * 4;
    int4 v = *reinterpret_cast<const int4*>(&g_hist[i4]);
    *reinterpret_cast<int4*>(&g_hist[i4]) = make_int4(0, 0, 0, 0);  // re-zero
    int tot = v.x + v.y + v.z + v.w;
    int s = tot;
    #pragma unroll
    for (int o = 1; o < 32; o <<= 1) {
        int x = __shfl_up_sync(0xffffffffu, s, o);
        if (lane >= o) s += x;
    }
    if (lane == 31) ws[w] = s;
    __syncthreads();
    if (w == 0 && lane < 8) {
        int y = ws[lane];
        #pragma unroll
        for (int o = 1; o < 8; o <<= 1) {
            int x = __shfl_up_sync(0xffu, y, o);
            if (lane >= o) y += x;
        }
        ws[lane] = y;
    }
    __syncthreads();
    int base = ((w > 0) ? ws[w - 1] : 0) + s - tot + g_bsum[blockIdx.x];
    int4 o4;
    o4.x = base;
    o4.y = base + v.x;
    o4.z = base + v.x + v.y;
    o4.w = base + v.x + v.y + v.z;
    *reinterpret_cast<int4*>(&g_binStart[i4]) = o4;
}

__global__ __launch_bounds__(256) void scatter_kernel(const float* __restrict__ xs) {
    int n = blockIdx.x * 256 + threadIdx.x;
    float tx = xs[n*3], ty = xs[n*3+1], tz = xs[n*3+2];
    int pos = atomicAdd(&g_binStart[point_key(tx, ty, tz)], 1);
    g_pxs[pos] = make_float4(tx, ty, tz, __int_as_float(n));
}

// ---------------- repack (fp16 x-pair chunks, 8B) ----------------
__global__ __launch_bounds__(256) void repack_kernel(const float* __restrict__ fg)
{
    int idx = blockIdx.x * 256 + threadIdx.x;          // over NGRIDS*CELLS
    int g = idx >> 18;
    int c = idx & (CELLS - 1);
    int x = c & (GS - 1);
    const float* base = fg + (size_t)g * 2 * CELLS;    // [F=2, D, H, W]

    float a0 = base[c];
    float a1 = base[CELLS + c];
    float b0 = 0.0f, b1 = 0.0f;
    if (x < GS - 1) {
        b0 = base[c + 1];
        b1 = base[CELLS + c + 1];
    }
    __half2 h0 = __floats2half2_rn(a0 * FSCALE, a1 * FSCALE);
    __half2 h1 = __floats2half2_rn(b0 * FSCALE, b1 * FSCALE);
    uint2 v;
    v.x = *reinterpret_cast<unsigned*>(&h0);
    v.y = *reinterpret_cast<unsigned*>(&h1);
    st64cs(&g_pk[idx], v);
}

// ---------------- sample ----------------
__global__ __launch_bounds__(256) void sample_kernel(
    const float* __restrict__ M,      // [64, 4, 4]
    float* __restrict__ out)          // [NPTS, 128]
{
    __shared__ float sM[NGRIDS * 16];
    int tid = threadIdx.x;
    for (int i = tid; i < NGRIDS * 16; i += 256) {
        float v = M[i];
        sM[i] = ((i & 3) == 3) ? 31.5f * (v + 1.0f) : 31.5f * v;
    }
    __syncthreads();

    int chunk = blockIdx.x >> 10;              // grid epoch (L2-resident slab)
    int t     = (blockIdx.x & (PBLK - 1)) * 256 + tid;

    float4 p = g_pxs[t];                       // sorted -> warp-coherent gathers
    float tx = p.x, ty = p.y, tz = p.z;
    int n = __float_as_int(p.w);

    float res[2 * GPC];

    #pragma unroll
    for (int j = 0; j < GPC; ++j) {
        int g = chunk * GPC + j;
        const float* m = sM + g * 16;
        float px = fmaf(m[0], tx, fmaf(m[1], ty, fmaf(m[2],  tz, m[3])));
        float py = fmaf(m[4], tx, fmaf(m[5], ty, fmaf(m[6],  tz, m[7])));
        float pz = fmaf(m[8], tx, fmaf(m[9], ty, fmaf(m[10], tz, m[11])));

        float wx0, wx1, w00, w01, w10, w11;
        int r00, r01, r10, r11;

        // Sorted points -> warp-uniform branch nearly everywhere.
        bool interior = (px >= 0.0f) & (px < 63.0f) &
                        (py >= 0.0f) & (py < 63.0f) &
                        (pz >= 0.0f) & (pz < 63.0f);
        if (interior) {
            int ix = (int)px, iy = (int)py, iz = (int)pz;
            float fx = px - (float)ix;
            float fy = py - (float)iy;
            float fz = pz - (float)iz;
            wx0 = 1.0f - fx; wx1 = fx;
            float wz0 = (1.0f - fz) * FINV;
            float wz1 = fz * FINV;
            w00 = wz0 * (1.0f - fy); w01 = wz0 * fy;
            w10 = wz1 * (1.0f - fy); w11 = wz1 * fy;
            int b = (iz * GS + iy) * GS + ix;
            r00 = b;            r01 = b + GS;
            r10 = b + GS * GS;  r11 = b + GS * GS + GS;
        } else {
            float fx0 = floorf(px), fy0 = floorf(py), fz0 = floorf(pz);
            float fx = px - fx0, fy = py - fy0, fz = pz - fz0;
            int ix = (int)fx0, iy = (int)fy0, iz = (int)fz0;

            bool inx = ((unsigned)ix < 64u);
            wx0 = inx ? (1.0f - fx) : ((ix == -1) ? fx : 0.0f);
            wx1 = inx ? fx : 0.0f;
            int xc = min(max(ix, 0), 63);

            float wy0 = ((unsigned)iy       < 64u) ? (1.0f - fy) : 0.0f;
            float wy1 = ((unsigned)(iy + 1) < 64u) ? fy          : 0.0f;
            int iy0c = min(max(iy,     0), 63);
            int iy1c = min(max(iy + 1, 0), 63);

            float wz0 = ((unsigned)iz       < 64u) ? (1.0f - fz) * FINV : 0.0f;
            float wz1 = ((unsigned)(iz + 1) < 64u) ? fz          * FINV : 0.0f;
            int iz0c = min(max(iz,     0), 63);
            int iz1c = min(max(iz + 1, 0), 63);

            w00 = wz0 * wy0; w01 = wz0 * wy1;
            w10 = wz1 * wy0; w11 = wz1 * wy1;
            r00 = (iz0c * GS + iy0c) * GS + xc;
            r01 = (iz0c * GS + iy1c) * GS + xc;
            r10 = (iz1c * GS + iy0c) * GS + xc;
            r11 = (iz1c * GS + iy1c) * GS + xc;
        }

        const uint2* gp = g_pk + (size_t)g * CELLS;
        uint2 c00 = ld64nc(gp + r00);
        uint2 c01 = ld64nc(gp + r01);
        uint2 c10 = ld64nc(gp + r10);
        uint2 c11 = ld64nc(gp + r11);

        // x-interp in half2 (pair = features), y/z reduction in fp32.
        __half2 hx0 = __float2half2_rn(wx0);
        __half2 hx1 = __float2half2_rn(wx1);
        __half2 m00 = __hfma2(*reinterpret_cast<__half2*>(&c00.y), hx1,
                      __hmul2(*reinterpret_cast<__half2*>(&c00.x), hx0));
        __half2 m01 = __hfma2(*reinterpret_cast<__half2*>(&c01.y), hx1,
                      __hmul2(*reinterpret_cast<__half2*>(&c01.x), hx0));
        __half2 m10 = __hfma2(*reinterpret_cast<__half2*>(&c10.y), hx1,
                      __hmul2(*reinterpret_cast<__half2*>(&c10.x), hx0));
        __half2 m11 = __hfma2(*reinterpret_cast<__half2*>(&c11.y), hx1,
                      __hmul2(*reinterpret_cast<__half2*>(&c11.x), hx0));

        float2 f00 = __half22float2(m00);
        float2 f01 = __half22float2(m01);
        float2 f10 = __half22float2(m10);
        float2 f11 = __half22float2(m11);

        float a0 = f00.x * w00;
        a0 = fmaf(f01.x, w01, a0);
        a0 = fmaf(f10.x, w10, a0);
        a0 = fmaf(f11.x, w11, a0);
        float a1 = f00.y * w00;
        a1 = fmaf(f01.y, w01, a1);
        a1 = fmaf(f10.y, w10, a1);
        a1 = fmaf(f11.y, w11, a1);

        res[2 * j]     = a0;
        res[2 * j + 1] = a1;
    }

    float* op = out + (size_t)n * (NGRIDS * 2) + chunk * (GPC * 2);
    st256cs_f(op, res);
    st256cs_f(op + 8, res + 8);
}

extern "C" void kernel_launch(void* const* d_in, const int* in_sizes, int n_in,
                              void* d_out, int out_size)
{
    const float* xs = (const float*)d_in[0];   // [262144, 3]
    const float* M  = (const float*)d_in[1];   // [64, 4, 4]
    const float* fg = (const float*)d_in[2];   // [64, 2, 64, 64, 64]
    float* out = (float*)d_out;                // [262144, 128]

    hist_kernel   <<<NPTS / 256, 256>>>(xs);
    scan1_kernel  <<<256, 256>>>();
    scan2_kernel  <<<1, 256>>>();
    scan3_kernel  <<<256, 256>>>();
    scatter_kernel<<<NPTS / 256, 256>>>(xs);
    repack_kernel <<<(NGRIDS * CELLS) / 256, 256>>>(fg);
    sample_kernel <<<NCHUNK * PBLK, 256>>>(M, out);
}